// round 3
// baseline (speedup 1.0000x reference)
#include <cuda_runtime.h>
#include <cooperative_groups.h>

namespace cg = cooperative_groups;

// Problem constants (fixed by the benchmark)
#define BATCH  512
#define TLEN   1024
#define DDIM   64
#define UDIM   128
#define ROWS   8          // batch rows per cluster
#define WSTRIDE 196       // 192 k-values + 4 pad words (bank decorrelation)

// Shared memory layout (floats)
//   Wsm   : 256 cols * 196          = 50176
//   bias  : 256                     -> @50176
//   h_buf : 2 * 8 * 128 = 2048      -> @50432
//   x_buf : 2 * 8 * 64  = 1024      -> @52480
//   c_sm  : 512                     -> @53504
//   g_sm  : 4 * 8 * 64 = 2048       -> @54016
// total 56064 floats = 224256 bytes
#define OFF_BIAS 50176
#define OFF_H    50432
#define OFF_X    52480
#define OFF_C    53504
#define OFF_G    54016
#define SMEM_FLOATS 56064
#define SMEM_BYTES  (SMEM_FLOATS * 4)

__device__ __forceinline__ float sigf(float x) {
    return 1.0f / (1.0f + __expf(-x));
}
__device__ __forceinline__ float tanhf_fast(float x) {
    // tanh(x) = 1 - 2/(1 + e^{2x}); stable for large |x| (e^{2x} -> inf or 0)
    return 1.0f - 2.0f / (1.0f + __expf(2.0f * x));
}

extern __shared__ float smem[];

__global__ void __launch_bounds__(256, 1) __cluster_dims__(2, 1, 1)
lstm_persistent_kernel(
    const float* __restrict__ x,
    const float* __restrict__ Wf, const float* __restrict__ Uf, const float* __restrict__ bf,
    const float* __restrict__ Wi, const float* __restrict__ Ui, const float* __restrict__ bi,
    const float* __restrict__ Wc, const float* __restrict__ Uc, const float* __restrict__ bc,
    const float* __restrict__ Wo, const float* __restrict__ Uo, const float* __restrict__ bo,
    float* __restrict__ out)
{
    float* Wsm  = smem;
    float* bsm  = smem + OFF_BIAS;
    float* hbuf = smem + OFF_H;
    float* xbuf = smem + OFF_X;
    float* csm  = smem + OFF_C;
    float* gsm  = smem + OFF_G;

    cg::cluster_group cluster = cg::this_cluster();
    const int q   = (int)cluster.block_rank();     // 0 or 1: which 64-col half of U this CTA owns
    const int tid = threadIdx.x;
    const int b0  = (blockIdx.x >> 1) * ROWS;      // batch-row base for this cluster

    // Peer CTA's h buffer (DSMEM) — push our computed h-half into it every step.
    float* hbuf_peer = cluster.map_shared_rank(hbuf, q ^ 1);

    // ---- one-time: load weights into smem, column-major [col][k], col = gate*64 + uu ----
    const float* Wg[4] = {Wf, Wi, Wc, Wo};
    const float* Ug[4] = {Uf, Ui, Uc, Uo};
    const float* bg[4] = {bf, bi, bc, bo};

    #pragma unroll
    for (int g = 0; g < 4; g++) {
        // input weights: k = d in [0,64)
        for (int idx = tid; idx < 64 * 64; idx += 256) {
            int d  = idx >> 6;
            int uu = idx & 63;
            Wsm[(g * 64 + uu) * WSTRIDE + d] = Wg[g][d * UDIM + q * 64 + uu];
        }
        // recurrent weights: k = 64 + kk, kk in [0,128)
        for (int idx = tid; idx < 128 * 64; idx += 256) {
            int kk = idx >> 6;
            int uu = idx & 63;
            Wsm[(g * 64 + uu) * WSTRIDE + 64 + kk] = Ug[g][kk * UDIM + q * 64 + uu];
        }
        if (tid < 64) bsm[g * 64 + tid] = bg[g][q * 64 + tid];
    }

    // init h = 0 (both parity buffers for safety), c = 0
    for (int idx = tid; idx < 2048; idx += 256) hbuf[idx] = 0.0f;
    for (int idx = tid; idx < 512;  idx += 256) csm[idx]  = 0.0f;

    // preload x_{t=0} into xbuf[0]: 512 floats, 2 per thread
    {
        int r0 = tid >> 6, d0 = tid & 63;
        xbuf[tid]       = x[(b0 + r0)     * (TLEN * DDIM) + d0];
        xbuf[tid + 256] = x[(b0 + r0 + 4) * (TLEN * DDIM) + d0];
    }
    __syncthreads();

    const int   j    = tid;                         // owned column: gate = j>>6, uu = j&63
    const float* wj  = Wsm + j * WSTRIDE;
    const int   gidx = (j >> 6) * 512 + (j & 63);   // base index into gsm for this column
    const float bj   = bsm[j];
    const int   r0   = tid >> 6;
    const int   d0   = tid & 63;

    for (int t = 0; t < TLEN; t++) {
        const int p = t & 1;

        // ---- prefetch x_{t+1} into registers (overlaps with FMA loop below) ----
        float pf0 = 0.0f, pf1 = 0.0f;
        if (t + 1 < TLEN) {
            pf0 = x[(b0 + r0)     * (TLEN * DDIM) + (t + 1) * DDIM + d0];
            pf1 = x[(b0 + r0 + 4) * (TLEN * DDIM) + (t + 1) * DDIM + d0];
        }

        // ---- gate preactivations: acc[r] = b + x_t . W[:,j] + h . U[:,j] ----
        float acc[8];
        #pragma unroll
        for (int r = 0; r < 8; r++) acc[r] = bj;

        const float4* w4 = (const float4*)wj;                 // k = 0..63 (x part)
        const float4* xb = (const float4*)(xbuf + p * 512);   // [8][16] float4
        #pragma unroll 8
        for (int k4 = 0; k4 < 16; k4++) {
            float4 w = w4[k4];
            #pragma unroll
            for (int r = 0; r < 8; r++) {
                float4 v = xb[r * 16 + k4];                   // warp-uniform broadcast
                acc[r] = fmaf(v.x, w.x, acc[r]);
                acc[r] = fmaf(v.y, w.y, acc[r]);
                acc[r] = fmaf(v.z, w.z, acc[r]);
                acc[r] = fmaf(v.w, w.w, acc[r]);
            }
        }

        const float4* wh = (const float4*)(wj + 64);          // k = 64..191 (h part)
        const float4* hb = (const float4*)(hbuf + p * 1024);  // [8][32] float4
        #pragma unroll 8
        for (int k4 = 0; k4 < 32; k4++) {
            float4 w = wh[k4];
            #pragma unroll
            for (int r = 0; r < 8; r++) {
                float4 v = hb[r * 32 + k4];                   // warp-uniform broadcast
                acc[r] = fmaf(v.x, w.x, acc[r]);
                acc[r] = fmaf(v.y, w.y, acc[r]);
                acc[r] = fmaf(v.z, w.z, acc[r]);
                acc[r] = fmaf(v.w, w.w, acc[r]);
            }
        }

        // publish preactivations for the gate-combine phase
        #pragma unroll
        for (int r = 0; r < 8; r++) gsm[gidx + r * 64] = acc[r];
        __syncthreads();

        // stash the x prefetch for step t+1 (other parity buffer — no readers now)
        if (t + 1 < TLEN) {
            xbuf[(p ^ 1) * 512 + tid]       = pf0;
            xbuf[(p ^ 1) * 512 + tid + 256] = pf1;
        }

        // ---- gate combine + state update; push h-half to self AND peer ----
        float* hl = hbuf      + (p ^ 1) * 1024;
        float* hp = hbuf_peer + (p ^ 1) * 1024;
        #pragma unroll
        for (int it = 0; it < 2; it++) {
            int i = tid + it * 256;                 // i = r*64 + uu, 512 state cells
            float gf = gsm[i];
            float gi = gsm[512 + i];
            float gc = gsm[1024 + i];
            float go = gsm[1536 + i];
            float fg = sigf(gf);
            float ig = sigf(gi);
            float ct = tanhf_fast(gc);
            float og = sigf(go);
            float cn = fmaf(fg, csm[i], ig * ct);
            csm[i]   = cn;
            float hn = og * tanhf_fast(cn);
            int r  = i >> 6;
            int uu = i & 63;
            hl[r * 128 + q * 64 + uu] = hn;
            hp[r * 128 + q * 64 + uu] = hn;         // DSMEM push to peer
        }

        cluster.sync();   // orders h/x/g buffers for the next step, cluster-wide
    }

    // final h lives in hbuf parity ((T-1)&1)^1 == 0
    #pragma unroll
    for (int it = 0; it < 2; it++) {
        int i  = tid + it * 256;
        int r  = i >> 6;
        int uu = i & 63;
        out[(b0 + r) * UDIM + q * 64 + uu] = hbuf[r * 128 + q * 64 + uu];
    }
}

extern "C" void kernel_launch(void* const* d_in, const int* in_sizes, int n_in,
                              void* d_out, int out_size)
{
    const float* x  = (const float*)d_in[0];
    const float* Wf = (const float*)d_in[1];
    const float* Uf = (const float*)d_in[2];
    const float* bf = (const float*)d_in[3];
    const float* Wi = (const float*)d_in[4];
    const float* Ui = (const float*)d_in[5];
    const float* bi = (const float*)d_in[6];
    const float* Wc = (const float*)d_in[7];
    const float* Uc = (const float*)d_in[8];
    const float* bc = (const float*)d_in[9];
    const float* Wo = (const float*)d_in[10];
    const float* Uo = (const float*)d_in[11];
    const float* bo = (const float*)d_in[12];
    float* out = (float*)d_out;

    cudaFuncSetAttribute(lstm_persistent_kernel,
                         cudaFuncAttributeMaxDynamicSharedMemorySize, SMEM_BYTES);

    // 64 clusters x 2 CTAs = 128 CTAs; each cluster owns 8 batch rows.
    lstm_persistent_kernel<<<128, 256, SMEM_BYTES>>>(
        x, Wf, Uf, bf, Wi, Ui, bi, Wc, Uc, bc, Wo, Uo, bo, out);
}

// round 5
// speedup vs baseline: 1.6319x; 1.6319x over previous
#include <cuda_runtime.h>
#include <cooperative_groups.h>

namespace cg = cooperative_groups;

typedef unsigned long long u64;

// Problem constants (fixed by the benchmark)
#define BATCH  512
#define TLEN   1024
#define DDIM   64
#define UDIM   128
#define ROWS   8          // batch rows per cluster
#define WSTRIDE 196       // 192 k-values + 4 pad words (bank decorrelation, 16B-aligned cols)

// Shared memory layout (floats)
//   Wsm   : 256 cols * 196          = 50176
//   bias  : 256                     -> @50176
//   h_buf : 2 * 8 * 128 = 2048      -> @50432
//   x_buf : 2 * 8 * 64  = 1024      -> @52480
//   c_sm  : 512                     -> @53504
//   g_sm  : 4 * 8 * 64 = 2048       -> @54016
// total 56064 floats = 224256 bytes
#define OFF_BIAS 50176
#define OFF_H    50432
#define OFF_X    52480
#define OFF_C    53504
#define OFF_G    54016
#define SMEM_FLOATS 56064
#define SMEM_BYTES  (SMEM_FLOATS * 4)

__device__ __forceinline__ float sigf(float x) {
    return 1.0f / (1.0f + __expf(-x));
}
__device__ __forceinline__ float tanhf_fast(float x) {
    return 1.0f - 2.0f / (1.0f + __expf(2.0f * x));
}

// ---- packed f32x2 helpers (PTX-only; ptxas never auto-fuses FFMA2) ----
__device__ __forceinline__ void fma2(u64& acc, u64 a, u64 b) {
    asm("fma.rn.f32x2 %0, %1, %2, %0;" : "+l"(acc) : "l"(a), "l"(b));
}
__device__ __forceinline__ u64 pack2(float lo, float hi) {
    u64 r;
    asm("mov.b64 %0, {%1, %2};" : "=l"(r) : "f"(lo), "f"(hi));
    return r;
}
__device__ __forceinline__ float fold2(u64 v) {
    float lo, hi;
    asm("mov.b64 {%0, %1}, %2;" : "=f"(lo), "=f"(hi) : "l"(v));
    return lo + hi;
}

extern __shared__ float smem[];

__global__ void __launch_bounds__(256, 1) __cluster_dims__(2, 1, 1)
lstm_persistent_kernel(
    const float* __restrict__ x,
    const float* __restrict__ Wf, const float* __restrict__ Uf, const float* __restrict__ bf,
    const float* __restrict__ Wi, const float* __restrict__ Ui, const float* __restrict__ bi,
    const float* __restrict__ Wc, const float* __restrict__ Uc, const float* __restrict__ bc,
    const float* __restrict__ Wo, const float* __restrict__ Uo, const float* __restrict__ bo,
    float* __restrict__ out)
{
    float* Wsm  = smem;
    float* bsm  = smem + OFF_BIAS;
    float* hbuf = smem + OFF_H;
    float* xbuf = smem + OFF_X;
    float* csm  = smem + OFF_C;
    float* gsm  = smem + OFF_G;

    cg::cluster_group cluster = cg::this_cluster();
    const int q   = (int)cluster.block_rank();     // 0/1: which 64-col half of U this CTA owns
    const int tid = threadIdx.x;
    const int b0  = (blockIdx.x >> 1) * ROWS;      // batch-row base for this cluster

    float* hbuf_peer = cluster.map_shared_rank(hbuf, q ^ 1);

    // ---- one-time: weights into smem, column-major [col][k], col = gate*64 + uu ----
    const float* Wg[4] = {Wf, Wi, Wc, Wo};
    const float* Ug[4] = {Uf, Ui, Uc, Uo};
    const float* bg[4] = {bf, bi, bc, bo};

    #pragma unroll
    for (int g = 0; g < 4; g++) {
        for (int idx = tid; idx < 64 * 64; idx += 256) {
            int d  = idx >> 6;
            int uu = idx & 63;
            Wsm[(g * 64 + uu) * WSTRIDE + d] = Wg[g][d * UDIM + q * 64 + uu];
        }
        for (int idx = tid; idx < 128 * 64; idx += 256) {
            int kk = idx >> 6;
            int uu = idx & 63;
            Wsm[(g * 64 + uu) * WSTRIDE + 64 + kk] = Ug[g][kk * UDIM + q * 64 + uu];
        }
        if (tid < 64) bsm[g * 64 + tid] = bg[g][q * 64 + tid];
    }

    for (int idx = tid; idx < 2048; idx += 256) hbuf[idx] = 0.0f;
    for (int idx = tid; idx < 512;  idx += 256) csm[idx]  = 0.0f;

    {
        int r0 = tid >> 6, d0 = tid & 63;
        xbuf[tid]       = x[(b0 + r0)     * (TLEN * DDIM) + d0];
        xbuf[tid + 256] = x[(b0 + r0 + 4) * (TLEN * DDIM) + d0];
    }
    __syncthreads();

    const int    j    = tid;                        // owned column: gate = j>>6, uu = j&63
    const float* wj   = Wsm + j * WSTRIDE;
    const int    gidx = (j >> 6) * 512 + (j & 63);
    const u64    bp   = pack2(bsm[j], 0.0f);        // bias pre-packed into lo half
    const int    r0   = tid >> 6;
    const int    d0   = tid & 63;

    for (int t = 0; t < TLEN; t++) {
        const int p = t & 1;

        // ---- prefetch x_{t+1} into registers (overlaps with FMA loop) ----
        float pf0 = 0.0f, pf1 = 0.0f;
        if (t + 1 < TLEN) {
            pf0 = x[(b0 + r0)     * (TLEN * DDIM) + (t + 1) * DDIM + d0];
            pf1 = x[(b0 + r0 + 4) * (TLEN * DDIM) + (t + 1) * DDIM + d0];
        }

        // ---- gate preactivations via packed f32x2 FMA (even/odd-k halves) ----
        u64 acc[8];
        #pragma unroll
        for (int r = 0; r < 8; r++) acc[r] = bp;

        // x part: k = 0..63  (16 x ulonglong2 per column)
        {
            const ulonglong2* w2 = (const ulonglong2*)wj;
            const ulonglong2* xb = (const ulonglong2*)(xbuf + p * 512);   // [8][16]
            #pragma unroll 8
            for (int k4 = 0; k4 < 16; k4++) {
                ulonglong2 w = w2[k4];
                #pragma unroll
                for (int r = 0; r < 8; r++) {
                    ulonglong2 v = xb[r * 16 + k4];   // warp-uniform broadcast
                    fma2(acc[r], v.x, w.x);
                    fma2(acc[r], v.y, w.y);
                }
            }
        }

        // h part: k = 64..191  (32 x ulonglong2 per column)
        {
            const ulonglong2* w2 = (const ulonglong2*)(wj + 64);
            const ulonglong2* hb = (const ulonglong2*)(hbuf + p * 1024);  // [8][32]
            #pragma unroll 8
            for (int k4 = 0; k4 < 32; k4++) {
                ulonglong2 w = w2[k4];
                #pragma unroll
                for (int r = 0; r < 8; r++) {
                    ulonglong2 v = hb[r * 32 + k4];   // warp-uniform broadcast
                    fma2(acc[r], v.x, w.x);
                    fma2(acc[r], v.y, w.y);
                }
            }
        }

        // publish preactivations (fold even/odd halves)
        #pragma unroll
        for (int r = 0; r < 8; r++) gsm[gidx + r * 64] = fold2(acc[r]);
        __syncthreads();

        // stash the x prefetch for step t+1 (other parity buffer)
        if (t + 1 < TLEN) {
            xbuf[(p ^ 1) * 512 + tid]       = pf0;
            xbuf[(p ^ 1) * 512 + tid + 256] = pf1;
        }

        // ---- gate combine + state update; push h-half to self AND peer ----
        float* hl = hbuf      + (p ^ 1) * 1024;
        float* hp = hbuf_peer + (p ^ 1) * 1024;
        #pragma unroll
        for (int it = 0; it < 2; it++) {
            int i = tid + it * 256;                 // i = r*64 + uu, 512 state cells
            float gf = gsm[i];
            float gi = gsm[512 + i];
            float gc = gsm[1024 + i];
            float go = gsm[1536 + i];
            float fg = sigf(gf);
            float ig = sigf(gi);
            float ct = tanhf_fast(gc);
            float og = sigf(go);
            float cn = fmaf(fg, csm[i], ig * ct);
            csm[i]   = cn;
            float hn = og * tanhf_fast(cn);
            int r  = i >> 6;
            int uu = i & 63;
            hl[r * 128 + q * 64 + uu] = hn;
            hp[r * 128 + q * 64 + uu] = hn;         // DSMEM push to peer
        }

        cluster.sync();   // orders h/x/g buffers for the next step, cluster-wide
    }

    // final h lives in hbuf parity 0
    #pragma unroll
    for (int it = 0; it < 2; it++) {
        int i  = tid + it * 256;
        int r  = i >> 6;
        int uu = i & 63;
        out[(b0 + r) * UDIM + q * 64 + uu] = hbuf[r * 128 + q * 64 + uu];
    }
}

extern "C" void kernel_launch(void* const* d_in, const int* in_sizes, int n_in,
                              void* d_out, int out_size)
{
    const float* x  = (const float*)d_in[0];
    const float* Wf = (const float*)d_in[1];
    const float* Uf = (const float*)d_in[2];
    const float* bf = (const float*)d_in[3];
    const float* Wi = (const float*)d_in[4];
    const float* Ui = (const float*)d_in[5];
    const float* bi = (const float*)d_in[6];
    const float* Wc = (const float*)d_in[7];
    const float* Uc = (const float*)d_in[8];
    const float* bc = (const float*)d_in[9];
    const float* Wo = (const float*)d_in[10];
    const float* Uo = (const float*)d_in[11];
    const float* bo = (const float*)d_in[12];
    float* out = (float*)d_out;

    cudaFuncSetAttribute(lstm_persistent_kernel,
                         cudaFuncAttributeMaxDynamicSharedMemorySize, SMEM_BYTES);

    // 64 clusters x 2 CTAs = 128 CTAs; each cluster owns 8 batch rows.
    lstm_persistent_kernel<<<128, 256, SMEM_BYTES>>>(
        x, Wf, Uf, bf, Wi, Ui, bi, Wc, Uc, bc, Wo, Uo, bo, out);
}

// round 6
// speedup vs baseline: 1.7468x; 1.0704x over previous
#include <cuda_runtime.h>
#include <cooperative_groups.h>

namespace cg = cooperative_groups;

typedef unsigned long long u64;

// Problem constants (fixed by the benchmark)
#define BATCH  512
#define TLEN   1024
#define DDIM   64
#define UDIM   128
#define ROWS   8          // batch rows per cluster
#define NTHR   128        // threads per CTA (4 warps; each thread owns 2 cols x 8 rows)
#define WSTRIDE 196       // 192 k-values + 4 pad words (bank decorrelation, 16B-aligned cols)

// Shared memory layout (floats)
//   Wsm   : 256 cols * 196          = 50176
//   bias  : 256                     -> @50176
//   h_buf : 2 * 8 * 128 = 2048      -> @50432
//   x_buf : 2 * 8 * 64  = 1024      -> @52480
//   c_sm  : 512                     -> @53504
//   g_sm  : 4 * 8 * 64 = 2048       -> @54016
// total 56064 floats = 224256 bytes
#define OFF_BIAS 50176
#define OFF_H    50432
#define OFF_X    52480
#define OFF_C    53504
#define OFF_G    54016
#define SMEM_FLOATS 56064
#define SMEM_BYTES  (SMEM_FLOATS * 4)

__device__ __forceinline__ float sigf(float x) {
    return 1.0f / (1.0f + __expf(-x));
}
__device__ __forceinline__ float tanhf_fast(float x) {
    return 1.0f - 2.0f / (1.0f + __expf(2.0f * x));
}

// ---- packed f32x2 helpers (PTX-only; ptxas never auto-fuses FFMA2) ----
__device__ __forceinline__ void fma2(u64& acc, u64 a, u64 b) {
    asm("fma.rn.f32x2 %0, %1, %2, %0;" : "+l"(acc) : "l"(a), "l"(b));
}
__device__ __forceinline__ u64 pack2(float lo, float hi) {
    u64 r;
    asm("mov.b64 %0, {%1, %2};" : "=l"(r) : "f"(lo), "f"(hi));
    return r;
}
__device__ __forceinline__ float fold2(u64 v) {
    float lo, hi;
    asm("mov.b64 {%0, %1}, %2;" : "=f"(lo), "=f"(hi) : "l"(v));
    return lo + hi;
}

extern __shared__ float smem[];

__global__ void __launch_bounds__(NTHR, 1) __cluster_dims__(2, 1, 1)
lstm_persistent_kernel(
    const float* __restrict__ x,
    const float* __restrict__ Wf, const float* __restrict__ Uf, const float* __restrict__ bf,
    const float* __restrict__ Wi, const float* __restrict__ Ui, const float* __restrict__ bi,
    const float* __restrict__ Wc, const float* __restrict__ Uc, const float* __restrict__ bc,
    const float* __restrict__ Wo, const float* __restrict__ Uo, const float* __restrict__ bo,
    float* __restrict__ out)
{
    float* Wsm  = smem;
    float* bsm  = smem + OFF_BIAS;
    float* hbuf = smem + OFF_H;
    float* xbuf = smem + OFF_X;
    float* csm  = smem + OFF_C;
    float* gsm  = smem + OFF_G;

    cg::cluster_group cluster = cg::this_cluster();
    const int q   = (int)cluster.block_rank();     // 0/1: which 64-col half of U this CTA owns
    const int tid = threadIdx.x;
    const int b0  = (blockIdx.x >> 1) * ROWS;      // batch-row base for this cluster

    float* hbuf_peer = cluster.map_shared_rank(hbuf, q ^ 1);

    // ---- one-time: weights into smem, column-major [col][k], col = gate*64 + uu ----
    const float* Wg[4] = {Wf, Wi, Wc, Wo};
    const float* Ug[4] = {Uf, Ui, Uc, Uo};
    const float* bg[4] = {bf, bi, bc, bo};

    #pragma unroll
    for (int g = 0; g < 4; g++) {
        for (int idx = tid; idx < 64 * 64; idx += NTHR) {
            int d  = idx >> 6;
            int uu = idx & 63;
            Wsm[(g * 64 + uu) * WSTRIDE + d] = Wg[g][d * UDIM + q * 64 + uu];
        }
        for (int idx = tid; idx < 128 * 64; idx += NTHR) {
            int kk = idx >> 6;
            int uu = idx & 63;
            Wsm[(g * 64 + uu) * WSTRIDE + 64 + kk] = Ug[g][kk * UDIM + q * 64 + uu];
        }
        if (tid < 64) bsm[g * 64 + tid] = bg[g][q * 64 + tid];
    }

    for (int idx = tid; idx < 2048; idx += NTHR) hbuf[idx] = 0.0f;
    for (int idx = tid; idx < 512;  idx += NTHR) csm[idx]  = 0.0f;

    // preload x_{t=0}: 512 floats, 4 per thread
    #pragma unroll
    for (int i = 0; i < 4; i++) {
        int idx = tid + i * NTHR;
        int r = idx >> 6, d = idx & 63;
        xbuf[idx] = x[(b0 + r) * (TLEN * DDIM) + d];
    }
    __syncthreads();

    // thread owns cols c0 = tid (gates f/i) and c1 = tid + 128 (gates c/o)
    const int    c0   = tid;
    const int    c1   = tid + 128;
    const float* wj0  = Wsm + c0 * WSTRIDE;
    const float* wj1  = Wsm + c1 * WSTRIDE;
    const int    uu   = tid & 63;
    const int    g0   = tid >> 6;            // 0 or 1
    const int    gidx0 = g0 * 512 + uu;      // gsm base for col c0
    const int    gidx1 = (g0 + 2) * 512 + uu;// gsm base for col c1
    const u64    bp0  = pack2(bsm[c0], 0.0f);
    const u64    bp1  = pack2(bsm[c1], 0.0f);

    for (int t = 0; t < TLEN; t++) {
        const int p = t & 1;

        // ---- prefetch x_{t+1} into registers (overlaps with FMA loop) ----
        float pf[4];
        #pragma unroll
        for (int i = 0; i < 4; i++) pf[i] = 0.0f;
        if (t + 1 < TLEN) {
            #pragma unroll
            for (int i = 0; i < 4; i++) {
                int idx = tid + i * NTHR;
                int r = idx >> 6, d = idx & 63;
                pf[i] = x[(b0 + r) * (TLEN * DDIM) + (t + 1) * DDIM + d];
            }
        }

        // ---- gate preactivations via packed f32x2 FMA; 2 cols share each broadcast ----
        u64 a0[8], a1[8];
        #pragma unroll
        for (int r = 0; r < 8; r++) { a0[r] = bp0; a1[r] = bp1; }

        // x part: k = 0..63 (16 ulonglong2 per column)
        {
            const ulonglong2* w20 = (const ulonglong2*)wj0;
            const ulonglong2* w21 = (const ulonglong2*)wj1;
            const ulonglong2* xb  = (const ulonglong2*)(xbuf + p * 512);   // [8][16]
            #pragma unroll 4
            for (int k4 = 0; k4 < 16; k4++) {
                ulonglong2 w0 = w20[k4];
                ulonglong2 w1 = w21[k4];
                #pragma unroll
                for (int r = 0; r < 8; r++) {
                    ulonglong2 v = xb[r * 16 + k4];   // warp-uniform broadcast, reused x2
                    fma2(a0[r], v.x, w0.x);
                    fma2(a0[r], v.y, w0.y);
                    fma2(a1[r], v.x, w1.x);
                    fma2(a1[r], v.y, w1.y);
                }
            }
        }

        // h part: k = 64..191 (32 ulonglong2 per column)
        {
            const ulonglong2* w20 = (const ulonglong2*)(wj0 + 64);
            const ulonglong2* w21 = (const ulonglong2*)(wj1 + 64);
            const ulonglong2* hb  = (const ulonglong2*)(hbuf + p * 1024);  // [8][32]
            #pragma unroll 4
            for (int k4 = 0; k4 < 32; k4++) {
                ulonglong2 w0 = w20[k4];
                ulonglong2 w1 = w21[k4];
                #pragma unroll
                for (int r = 0; r < 8; r++) {
                    ulonglong2 v = hb[r * 32 + k4];   // warp-uniform broadcast, reused x2
                    fma2(a0[r], v.x, w0.x);
                    fma2(a0[r], v.y, w0.y);
                    fma2(a1[r], v.x, w1.x);
                    fma2(a1[r], v.y, w1.y);
                }
            }
        }

        // publish preactivations (fold even/odd halves)
        #pragma unroll
        for (int r = 0; r < 8; r++) {
            gsm[gidx0 + r * 64] = fold2(a0[r]);
            gsm[gidx1 + r * 64] = fold2(a1[r]);
        }
        __syncthreads();

        // stash the x prefetch for step t+1 (other parity buffer)
        if (t + 1 < TLEN) {
            #pragma unroll
            for (int i = 0; i < 4; i++) xbuf[(p ^ 1) * 512 + tid + i * NTHR] = pf[i];
        }

        // ---- gate combine + state update; push h-half to self AND peer ----
        float* hl = hbuf      + (p ^ 1) * 1024;
        float* hp = hbuf_peer + (p ^ 1) * 1024;
        #pragma unroll
        for (int it = 0; it < 4; it++) {
            int i = tid + it * NTHR;                // i = r*64 + uu, 512 state cells
            float gf = gsm[i];
            float gi = gsm[512 + i];
            float gc = gsm[1024 + i];
            float go = gsm[1536 + i];
            float fg = sigf(gf);
            float ig = sigf(gi);
            float ct = tanhf_fast(gc);
            float og = sigf(go);
            float cn = fmaf(fg, csm[i], ig * ct);
            csm[i]   = cn;
            float hn = og * tanhf_fast(cn);
            int r  = i >> 6;
            int u2 = i & 63;
            hl[r * 128 + q * 64 + u2] = hn;
            hp[r * 128 + q * 64 + u2] = hn;         // DSMEM push to peer
        }

        cluster.sync();   // orders h/x/g buffers for the next step, cluster-wide
    }

    // final h lives in hbuf parity 0
    #pragma unroll
    for (int it = 0; it < 4; it++) {
        int i  = tid + it * NTHR;
        int r  = i >> 6;
        int u2 = i & 63;
        out[(b0 + r) * UDIM + q * 64 + u2] = hbuf[r * 128 + q * 64 + u2];
    }
}

extern "C" void kernel_launch(void* const* d_in, const int* in_sizes, int n_in,
                              void* d_out, int out_size)
{
    const float* x  = (const float*)d_in[0];
    const float* Wf = (const float*)d_in[1];
    const float* Uf = (const float*)d_in[2];
    const float* bf = (const float*)d_in[3];
    const float* Wi = (const float*)d_in[4];
    const float* Ui = (const float*)d_in[5];
    const float* bi = (const float*)d_in[6];
    const float* Wc = (const float*)d_in[7];
    const float* Uc = (const float*)d_in[8];
    const float* bc = (const float*)d_in[9];
    const float* Wo = (const float*)d_in[10];
    const float* Uo = (const float*)d_in[11];
    const float* bo = (const float*)d_in[12];
    float* out = (float*)d_out;

    cudaFuncSetAttribute(lstm_persistent_kernel,
                         cudaFuncAttributeMaxDynamicSharedMemorySize, SMEM_BYTES);

    // 64 clusters x 2 CTAs = 128 CTAs; each cluster owns 8 batch rows.
    lstm_persistent_kernel<<<128, NTHR, SMEM_BYTES>>>(
        x, Wf, Uf, bf, Wi, Ui, bi, Wc, Uc, bc, Wo, Uo, bo, out);
}

// round 10
// speedup vs baseline: 2.1552x; 1.2338x over previous
#include <cuda_runtime.h>
#include <cooperative_groups.h>

namespace cg = cooperative_groups;

typedef unsigned long long u64;

// Problem constants (fixed by the benchmark)
#define BATCH  512
#define TLEN   1024
#define DDIM   64
#define UDIM   128
#define ROWS   8          // batch rows per cluster
#define NTHR   256        // 8 warps; k-split: warps 0-3 -> k[0,96), warps 4-7 -> k[96,192)
#define WSTRIDE 196       // 192 k-values + 4 pad words (conflict-free: 196 % 32 == 4)

// Shared memory layout (floats)
//   Wsm   : 256 cols * 196          = 50176
//   h_buf : 2 * 8 * 128 = 2048      -> @50176
//   x_buf : 2 * 8 * 64  = 1024      -> @52224
//   c_sm  : 512                     -> @53248
//   g_sm  : 2 * 2048 = 4096         -> @53760   (two partial banks, one per k-half)
//   bias  : 256 (ALIASES g_sm; consumed into regs before first g_sm write)
// total 57856 floats = 231424 bytes (<= 232448 opt-in cap)
#define OFF_H    50176
#define OFF_X    52224
#define OFF_C    53248
#define OFF_G    53760
#define OFF_BIAS OFF_G
#define SMEM_FLOATS 57856
#define SMEM_BYTES  (SMEM_FLOATS * 4)

__device__ __forceinline__ float sigf(float x) {
    return 1.0f / (1.0f + __expf(-x));
}
__device__ __forceinline__ float tanhf_fast(float x) {
    return 1.0f - 2.0f / (1.0f + __expf(2.0f * x));
}

// ---- packed f32x2 helpers (PTX-only; ptxas never auto-fuses FFMA2) ----
__device__ __forceinline__ void fma2(u64& acc, u64 a, u64 b) {
    asm("fma.rn.f32x2 %0, %1, %2, %0;" : "+l"(acc) : "l"(a), "l"(b));
}
__device__ __forceinline__ u64 pack2(float lo, float hi) {
    u64 r;
    asm("mov.b64 %0, {%1, %2};" : "=l"(r) : "f"(lo), "f"(hi));
    return r;
}
__device__ __forceinline__ float fold2(u64 v) {
    float lo, hi;
    asm("mov.b64 {%0, %1}, %2;" : "=f"(lo), "=f"(hi) : "l"(v));
    return lo + hi;
}

extern __shared__ float smem[];

__global__ void __launch_bounds__(NTHR, 1) __cluster_dims__(2, 1, 1)
lstm_persistent_kernel(
    const float* __restrict__ x,
    const float* __restrict__ Wf, const float* __restrict__ Uf, const float* __restrict__ bf,
    const float* __restrict__ Wi, const float* __restrict__ Ui, const float* __restrict__ bi,
    const float* __restrict__ Wc, const float* __restrict__ Uc, const float* __restrict__ bc,
    const float* __restrict__ Wo, const float* __restrict__ Uo, const float* __restrict__ bo,
    float* __restrict__ out)
{
    float* Wsm  = smem;
    float* hbuf = smem + OFF_H;
    float* xbuf = smem + OFF_X;
    float* csm  = smem + OFF_C;
    float* gsm  = smem + OFF_G;
    float* bsm  = smem + OFF_BIAS;   // aliases gsm; valid only until first gsm write

    cg::cluster_group cluster = cg::this_cluster();
    const int q   = (int)cluster.block_rank();     // 0/1: which 64-col half of U this CTA owns
    const int tid = threadIdx.x;
    const int b0  = (blockIdx.x >> 1) * ROWS;      // batch-row base for this cluster

    float* hbuf_peer = cluster.map_shared_rank(hbuf, q ^ 1);

    // ---- one-time: weights into smem, column-major [col][k], col = gate*64 + uu ----
    const float* Wg[4] = {Wf, Wi, Wc, Wo};
    const float* Ug[4] = {Uf, Ui, Uc, Uo};
    const float* bg[4] = {bf, bi, bc, bo};

    #pragma unroll
    for (int g = 0; g < 4; g++) {
        for (int idx = tid; idx < 64 * 64; idx += NTHR) {
            int d  = idx >> 6;
            int uu = idx & 63;
            Wsm[(g * 64 + uu) * WSTRIDE + d] = Wg[g][d * UDIM + q * 64 + uu];
        }
        for (int idx = tid; idx < 128 * 64; idx += NTHR) {
            int kk = idx >> 6;
            int uu = idx & 63;
            Wsm[(g * 64 + uu) * WSTRIDE + 64 + kk] = Ug[g][kk * UDIM + q * 64 + uu];
        }
        if (tid < 64) bsm[g * 64 + tid] = bg[g][q * 64 + tid];
    }

    for (int idx = tid; idx < 2048; idx += NTHR) hbuf[idx] = 0.0f;
    for (int idx = tid; idx < 512;  idx += NTHR) csm[idx]  = 0.0f;

    // preload x_{t=0}: 512 floats, 2 per thread
    #pragma unroll
    for (int i = 0; i < 2; i++) {
        int idx = tid + i * NTHR;
        int r = idx >> 6, d = idx & 63;
        xbuf[idx] = x[(b0 + r) * (TLEN * DDIM) + d];
    }
    __syncthreads();

    // k-split ownership: half = tid>>7 (0: x + h[0:32); 1: h[32:128))
    // thread covers cols c0 = (tid&127) [gates f/i] and c1 = c0+128 [gates c/o], all 8 rows.
    const int    half = tid >> 7;
    const int    ct   = tid & 127;
    const int    c0   = ct;
    const int    c1   = ct + 128;
    const float* wb0  = Wsm + c0 * WSTRIDE + half * 96;   // this half's 96-word k-slice
    const float* wb1  = Wsm + c1 * WSTRIDE + half * 96;
    const int    uu   = ct & 63;
    const int    g0   = ct >> 6;                 // 0 or 1
    const int    pb   = half * 2048;             // partial bank
    const int    gidx0 = pb + g0 * 512 + uu;
    const int    gidx1 = pb + (g0 + 2) * 512 + uu;
    // bias goes only into half 0's partials (bsm aliases gsm -> consume now, then barrier)
    const u64    bp0  = (half == 0) ? pack2(bsm[c0], 0.0f) : 0ull;
    const u64    bp1  = (half == 0) ? pack2(bsm[c1], 0.0f) : 0ull;
    __syncthreads();   // all bias reads complete before first gsm write

    for (int t = 0; t < TLEN; t++) {
        const int p = t & 1;

        // ---- prefetch x_{t+1} into registers (overlaps with FMA loop) ----
        float pf0 = 0.0f, pf1 = 0.0f;
        if (t + 1 < TLEN) {
            int r1 = tid >> 6, d1 = tid & 63;          // idx = tid
            pf0 = x[(b0 + r1)     * (TLEN * DDIM) + (t + 1) * DDIM + d1];
            pf1 = x[(b0 + r1 + 4) * (TLEN * DDIM) + (t + 1) * DDIM + d1];  // idx = tid+256
        }

        // ---- partial gate preactivations for this thread's k-slice ----
        u64 a0[8], a1[8];
        #pragma unroll
        for (int r = 0; r < 8; r++) { a0[r] = bp0; a1[r] = bp1; }

        const ulonglong2* w20 = (const ulonglong2*)wb0;
        const ulonglong2* w21 = (const ulonglong2*)wb1;

        if (half == 0) {
            // x part: k = 0..63 (16 ulonglong2)
            const ulonglong2* xb = (const ulonglong2*)(xbuf + p * 512);   // [8][16]
            #pragma unroll 8
            for (int k4 = 0; k4 < 16; k4++) {
                ulonglong2 w0 = w20[k4];
                ulonglong2 w1 = w21[k4];
                #pragma unroll
                for (int r = 0; r < 8; r++) {
                    ulonglong2 v = xb[r * 16 + k4];   // warp-uniform broadcast
                    fma2(a0[r], v.x, w0.x);
                    fma2(a0[r], v.y, w0.y);
                    fma2(a1[r], v.x, w1.x);
                    fma2(a1[r], v.y, w1.y);
                }
            }
            // h part: h[0:32) -> hb k4 = 0..7, weights at slice words 64..95
            const ulonglong2* hb = (const ulonglong2*)(hbuf + p * 1024);  // [8][32]
            #pragma unroll 8
            for (int k4 = 0; k4 < 8; k4++) {
                ulonglong2 w0 = w20[16 + k4];
                ulonglong2 w1 = w21[16 + k4];
                #pragma unroll
                for (int r = 0; r < 8; r++) {
                    ulonglong2 v = hb[r * 32 + k4];
                    fma2(a0[r], v.x, w0.x);
                    fma2(a0[r], v.y, w0.y);
                    fma2(a1[r], v.x, w1.x);
                    fma2(a1[r], v.y, w1.y);
                }
            }
        } else {
            // h part: h[32:128) -> hb k4 = 8..31, weights = this slice's 24 ulonglong2
            const ulonglong2* hb = (const ulonglong2*)(hbuf + p * 1024);  // [8][32]
            #pragma unroll 8
            for (int k4 = 0; k4 < 24; k4++) {
                ulonglong2 w0 = w20[k4];
                ulonglong2 w1 = w21[k4];
                #pragma unroll
                for (int r = 0; r < 8; r++) {
                    ulonglong2 v = hb[r * 32 + 8 + k4];
                    fma2(a0[r], v.x, w0.x);
                    fma2(a0[r], v.y, w0.y);
                    fma2(a1[r], v.x, w1.x);
                    fma2(a1[r], v.y, w1.y);
                }
            }
        }

        // publish partials (fold even/odd halves); banks: lanes hit consecutive uu
        #pragma unroll
        for (int r = 0; r < 8; r++) {
            gsm[gidx0 + r * 64] = fold2(a0[r]);
            gsm[gidx1 + r * 64] = fold2(a1[r]);
        }
        __syncthreads();

        // stash the x prefetch for step t+1 (other parity buffer)
        if (t + 1 < TLEN) {
            xbuf[(p ^ 1) * 512 + tid]       = pf0;
            xbuf[(p ^ 1) * 512 + tid + 256] = pf1;
        }

        // ---- combine k-half partials + gate math; push h-half to self AND peer ----
        float* hl = hbuf      + (p ^ 1) * 1024;
        float* hp = hbuf_peer + (p ^ 1) * 1024;
        #pragma unroll
        for (int it = 0; it < 2; it++) {
            int i = tid + it * NTHR;                // i = r*64 + uu, 512 state cells
            float gf = gsm[i]        + gsm[2048 + i];
            float gi = gsm[512 + i]  + gsm[2560 + i];
            float gc = gsm[1024 + i] + gsm[3072 + i];
            float go = gsm[1536 + i] + gsm[3584 + i];
            float fg = sigf(gf);
            float ig = sigf(gi);
            float ctl = tanhf_fast(gc);
            float og = sigf(go);
            float cn = fmaf(fg, csm[i], ig * ctl);
            csm[i]   = cn;
            float hn = og * tanhf_fast(cn);
            int r  = i >> 6;
            int u2 = i & 63;
            hl[r * 128 + q * 64 + u2] = hn;
            hp[r * 128 + q * 64 + u2] = hn;         // DSMEM push to peer
        }

        cluster.sync();   // orders h/x/g buffers for the next step, cluster-wide
    }

    // final h lives in hbuf parity 0
    #pragma unroll
    for (int it = 0; it < 2; it++) {
        int i  = tid + it * NTHR;
        int r  = i >> 6;
        int u2 = i & 63;
        out[(b0 + r) * UDIM + q * 64 + u2] = hbuf[r * 128 + q * 64 + u2];
    }
}

extern "C" void kernel_launch(void* const* d_in, const int* in_sizes, int n_in,
                              void* d_out, int out_size)
{
    const float* x  = (const float*)d_in[0];
    const float* Wf = (const float*)d_in[1];
    const float* Uf = (const float*)d_in[2];
    const float* bf = (const float*)d_in[3];
    const float* Wi = (const float*)d_in[4];
    const float* Ui = (const float*)d_in[5];
    const float* bi = (const float*)d_in[6];
    const float* Wc = (const float*)d_in[7];
    const float* Uc = (const float*)d_in[8];
    const float* bc = (const float*)d_in[9];
    const float* Wo = (const float*)d_in[10];
    const float* Uo = (const float*)d_in[11];
    const float* bo = (const float*)d_in[12];
    float* out = (float*)d_out;

    cudaFuncSetAttribute(lstm_persistent_kernel,
                         cudaFuncAttributeMaxDynamicSharedMemorySize, SMEM_BYTES);

    // 64 clusters x 2 CTAs = 128 CTAs; each cluster owns 8 batch rows.
    lstm_persistent_kernel<<<128, NTHR, SMEM_BYTES>>>(
        x, Wf, Uf, bf, Wi, Ui, bi, Wc, Uc, bc, Wo, Uo, bo, out);
}

// round 11
// speedup vs baseline: 2.2654x; 1.0511x over previous
#include <cuda_runtime.h>
#include <cooperative_groups.h>

namespace cg = cooperative_groups;

typedef unsigned long long u64;

// Problem constants (fixed by the benchmark)
#define BATCH  512
#define TLEN   1024
#define DDIM   64
#define UDIM   128
#define ROWS   8          // batch rows per cluster
#define NTHR   256        // 8 warps; k-split across two 128-thread halves
#define WSTRIDE 196       // 192 k-values + 4 pad words (conflict-free: 196 % 32 == 4)

// Shared memory layout (floats)
//   Wsm   : 256 cols * 196          = 50176
//   h_buf : 2 * 8 * 128 = 2048      -> @50176
//   x_buf : 2 * 8 * 64  = 1024      -> @52224
//   c_sm  : 512                     -> @53248
//   g_sm  : 2 * 2048 = 4096         -> @53760   (two partial banks, one per k-half)
//   bias  : 256 (ALIASES g_sm; consumed into regs before first g_sm write)
// total 57856 floats = 231424 bytes (<= 232448 opt-in cap)
#define OFF_H    50176
#define OFF_X    52224
#define OFF_C    53248
#define OFF_G    53760
#define OFF_BIAS OFF_G
#define SMEM_FLOATS 57856
#define SMEM_BYTES  (SMEM_FLOATS * 4)

// Split cluster barrier: arrive (release) at end of combine, wait (acquire)
// deferred until the peer-h part of the NEXT step's FMA phase.
#define CLUSTER_ARRIVE() asm volatile("barrier.cluster.arrive.aligned;" ::: "memory")
#define CLUSTER_WAIT()   asm volatile("barrier.cluster.wait.aligned;"   ::: "memory")

__device__ __forceinline__ float sigf(float x) {
    return 1.0f / (1.0f + __expf(-x));
}
__device__ __forceinline__ float tanhf_fast(float x) {
    return 1.0f - 2.0f / (1.0f + __expf(2.0f * x));
}

// ---- packed f32x2 helpers (PTX-only; ptxas never auto-fuses FFMA2) ----
__device__ __forceinline__ void fma2(u64& acc, u64 a, u64 b) {
    asm("fma.rn.f32x2 %0, %1, %2, %0;" : "+l"(acc) : "l"(a), "l"(b));
}
__device__ __forceinline__ u64 pack2(float lo, float hi) {
    u64 r;
    asm("mov.b64 %0, {%1, %2};" : "=l"(r) : "f"(lo), "f"(hi));
    return r;
}
__device__ __forceinline__ float fold2(u64 v) {
    float lo, hi;
    asm("mov.b64 {%0, %1}, %2;" : "=f"(lo), "=f"(hi) : "l"(v));
    return lo + hi;
}

extern __shared__ float smem[];

__global__ void __launch_bounds__(NTHR, 1) __cluster_dims__(2, 1, 1)
lstm_persistent_kernel(
    const float* __restrict__ x,
    const float* __restrict__ Wf, const float* __restrict__ Uf, const float* __restrict__ bf,
    const float* __restrict__ Wi, const float* __restrict__ Ui, const float* __restrict__ bi,
    const float* __restrict__ Wc, const float* __restrict__ Uc, const float* __restrict__ bc,
    const float* __restrict__ Wo, const float* __restrict__ Uo, const float* __restrict__ bo,
    float* __restrict__ out)
{
    float* Wsm  = smem;
    float* hbuf = smem + OFF_H;
    float* xbuf = smem + OFF_X;
    float* csm  = smem + OFF_C;
    float* gsm  = smem + OFF_G;
    float* bsm  = smem + OFF_BIAS;   // aliases gsm; valid only until first gsm write

    cg::cluster_group cluster = cg::this_cluster();
    const int q   = (int)cluster.block_rank();     // 0/1: which 64-col half of U this CTA owns
    const int tid = threadIdx.x;
    const int b0  = (blockIdx.x >> 1) * ROWS;      // batch-row base for this cluster

    float* hbuf_peer = cluster.map_shared_rank(hbuf, q ^ 1);

    // ---- one-time: weights into smem, column-major [col][k], col = gate*64 + uu ----
    const float* Wg[4] = {Wf, Wi, Wc, Wo};
    const float* Ug[4] = {Uf, Ui, Uc, Uo};
    const float* bg[4] = {bf, bi, bc, bo};

    #pragma unroll
    for (int g = 0; g < 4; g++) {
        for (int idx = tid; idx < 64 * 64; idx += NTHR) {
            int d  = idx >> 6;
            int uu = idx & 63;
            Wsm[(g * 64 + uu) * WSTRIDE + d] = Wg[g][d * UDIM + q * 64 + uu];
        }
        for (int idx = tid; idx < 128 * 64; idx += NTHR) {
            int kk = idx >> 6;
            int uu = idx & 63;
            Wsm[(g * 64 + uu) * WSTRIDE + 64 + kk] = Ug[g][kk * UDIM + q * 64 + uu];
        }
        if (tid < 64) bsm[g * 64 + tid] = bg[g][q * 64 + tid];
    }

    for (int idx = tid; idx < 2048; idx += NTHR) hbuf[idx] = 0.0f;
    for (int idx = tid; idx < 512;  idx += NTHR) csm[idx]  = 0.0f;

    // preload x_{t=0}: 512 floats, 2 per thread
    #pragma unroll
    for (int i = 0; i < 2; i++) {
        int idx = tid + i * NTHR;
        int r = idx >> 6, d = idx & 63;
        xbuf[idx] = x[(b0 + r) * (TLEN * DDIM) + d];
    }
    __syncthreads();

    // k-split ownership (single uniform code path, runtime slice bases):
    //   half = tid>>7; thread covers cols c0 = tid&127 (gates f/i) and c1 = c0+128
    //   (gates c/o), 8 rows each, over 24 k4-slices:
    //     x slice      : j  = half*8      + jj,  jj=0..7   (k 0..63, no dependency)
    //     local-h slice: m  = q*16+half*8 + jj             (h produced by THIS CTA)
    //     peer-h slice : m' = (q^1)*16+half*8 + jj         (h pushed by peer -> after wait)
    const int    half = tid >> 7;
    const int    ct   = tid & 127;
    const int    c0   = ct;
    const int    c1   = ct + 128;
    const ulonglong2* W20 = (const ulonglong2*)(Wsm + c0 * WSTRIDE);
    const ulonglong2* W21 = (const ulonglong2*)(Wsm + c1 * WSTRIDE);
    const int    xbase = half * 8;
    const int    mloc  = q * 16 + half * 8;
    const int    mpeer = (q ^ 1) * 16 + half * 8;
    const int    uu   = ct & 63;
    const int    g0   = ct >> 6;                 // 0 or 1
    const int    pb   = half * 2048;             // partial bank
    const int    gidx0 = pb + g0 * 512 + uu;
    const int    gidx1 = pb + (g0 + 2) * 512 + uu;
    // bias goes only into half 0's partials (bsm aliases gsm -> consume now, then barrier)
    const u64    bp0  = (half == 0) ? pack2(bsm[c0], 0.0f) : 0ull;
    const u64    bp1  = (half == 0) ? pack2(bsm[c1], 0.0f) : 0ull;
    __syncthreads();   // all bias reads complete before first gsm write

    CLUSTER_ARRIVE();  // seed the arrive/wait pipeline (matches step-0 wait)

    for (int t = 0; t < TLEN; t++) {
        const int p = t & 1;

        // ---- prefetch x_{t+1} into registers (overlaps with whole FMA phase) ----
        float pf0 = 0.0f, pf1 = 0.0f;
        if (t + 1 < TLEN) {
            int r1 = tid >> 6, d1 = tid & 63;          // idx = tid
            pf0 = x[(b0 + r1)     * (TLEN * DDIM) + (t + 1) * DDIM + d1];
            pf1 = x[(b0 + r1 + 4) * (TLEN * DDIM) + (t + 1) * DDIM + d1];  // idx = tid+256
        }

        u64 a0[8], a1[8];
        #pragma unroll
        for (int r = 0; r < 8; r++) { a0[r] = bp0; a1[r] = bp1; }

        const ulonglong2* xb = (const ulonglong2*)(xbuf + p * 512);    // [8][16]
        const ulonglong2* hb = (const ulonglong2*)(hbuf + p * 1024);   // [8][32]

        // ---- x part (no recurrent dependency) ----
        #pragma unroll
        for (int jj = 0; jj < 8; jj++) {
            int j = xbase + jj;
            ulonglong2 w0 = W20[j];
            ulonglong2 w1 = W21[j];
            #pragma unroll
            for (int r = 0; r < 8; r++) {
                ulonglong2 v = xb[r * 16 + j];        // warp-uniform broadcast
                fma2(a0[r], v.x, w0.x);
                fma2(a0[r], v.y, w0.y);
                fma2(a1[r], v.x, w1.x);
                fma2(a1[r], v.y, w1.y);
            }
        }

        // ---- locally-produced h half (ordered by last step's B2 syncthreads) ----
        #pragma unroll
        for (int jj = 0; jj < 8; jj++) {
            int m = mloc + jj;
            ulonglong2 w0 = W20[16 + m];
            ulonglong2 w1 = W21[16 + m];
            #pragma unroll
            for (int r = 0; r < 8; r++) {
                ulonglong2 v = hb[r * 32 + m];
                fma2(a0[r], v.x, w0.x);
                fma2(a0[r], v.y, w0.y);
                fma2(a1[r], v.x, w1.x);
                fma2(a1[r], v.y, w1.y);
            }
        }

        // ---- now (and only now) we need the peer's pushed h half ----
        CLUSTER_WAIT();   // acquire: peer's DSMEM h stores of step t-1 visible

        #pragma unroll
        for (int jj = 0; jj < 8; jj++) {
            int m = mpeer + jj;
            ulonglong2 w0 = W20[16 + m];
            ulonglong2 w1 = W21[16 + m];
            #pragma unroll
            for (int r = 0; r < 8; r++) {
                ulonglong2 v = hb[r * 32 + m];
                fma2(a0[r], v.x, w0.x);
                fma2(a0[r], v.y, w0.y);
                fma2(a1[r], v.x, w1.x);
                fma2(a1[r], v.y, w1.y);
            }
        }

        // publish partials (fold even/odd halves)
        #pragma unroll
        for (int r = 0; r < 8; r++) {
            gsm[gidx0 + r * 64] = fold2(a0[r]);
            gsm[gidx1 + r * 64] = fold2(a1[r]);
        }
        __syncthreads();                              // B1: gsm ready

        // stash the x prefetch for step t+1 (other parity buffer)
        if (t + 1 < TLEN) {
            xbuf[(p ^ 1) * 512 + tid]       = pf0;
            xbuf[(p ^ 1) * 512 + tid + 256] = pf1;
        }

        // ---- combine k-half partials + gate math; push h-half to self AND peer ----
        float* hl = hbuf      + (p ^ 1) * 1024;
        float* hp = hbuf_peer + (p ^ 1) * 1024;
        #pragma unroll
        for (int it = 0; it < 2; it++) {
            int i = tid + it * NTHR;                  // i = r*64 + uu, 512 state cells
            float gf = gsm[i]        + gsm[2048 + i];
            float gi = gsm[512 + i]  + gsm[2560 + i];
            float gc = gsm[1024 + i] + gsm[3072 + i];
            float go = gsm[1536 + i] + gsm[3584 + i];
            float fg = sigf(gf);
            float ig = sigf(gi);
            float ctl = tanhf_fast(gc);
            float og = sigf(go);
            float cn = fmaf(fg, csm[i], ig * ctl);
            csm[i]   = cn;
            float hn = og * tanhf_fast(cn);
            int r  = i >> 6;
            int u2 = i & 63;
            hl[r * 128 + q * 64 + u2] = hn;
            hp[r * 128 + q * 64 + u2] = hn;           // DSMEM push to peer
        }
        __syncthreads();                              // B2: local h/x writes ordered

        CLUSTER_ARRIVE();  // release: our pushes to peer are published; wait deferred
    }

    CLUSTER_WAIT();        // drain final arrives; peer done touching our smem

    // final h lives in hbuf parity 0; each CTA wrote its own q-half locally
    #pragma unroll
    for (int it = 0; it < 2; it++) {
        int i  = tid + it * NTHR;
        int r  = i >> 6;
        int u2 = i & 63;
        out[(b0 + r) * UDIM + q * 64 + u2] = hbuf[r * 128 + q * 64 + u2];
    }
}

extern "C" void kernel_launch(void* const* d_in, const int* in_sizes, int n_in,
                              void* d_out, int out_size)
{
    const float* x  = (const float*)d_in[0];
    const float* Wf = (const float*)d_in[1];
    const float* Uf = (const float*)d_in[2];
    const float* bf = (const float*)d_in[3];
    const float* Wi = (const float*)d_in[4];
    const float* Ui = (const float*)d_in[5];
    const float* bi = (const float*)d_in[6];
    const float* Wc = (const float*)d_in[7];
    const float* Uc = (const float*)d_in[8];
    const float* bc = (const float*)d_in[9];
    const float* Wo = (const float*)d_in[10];
    const float* Uo = (const float*)d_in[11];
    const float* bo = (const float*)d_in[12];
    float* out = (float*)d_out;

    cudaFuncSetAttribute(lstm_persistent_kernel,
                         cudaFuncAttributeMaxDynamicSharedMemorySize, SMEM_BYTES);

    // 64 clusters x 2 CTAs = 128 CTAs; each cluster owns 8 batch rows.
    lstm_persistent_kernel<<<128, NTHR, SMEM_BYTES>>>(
        x, Wf, Uf, bf, Wi, Ui, bi, Wc, Uc, bc, Wo, Uo, bo, out);
}